// round 10
// baseline (speedup 1.0000x reference)
#include <cuda_runtime.h>
#include <math.h>

// Shape-specialized: H=1024, N_HALF=32, L=4096, CHANNELS=1
// Grid = 2048: block b handles h = b>>1, l-range half = b&1 (2048 each).
#define HH    1024
#define NH    32
#define TPB   128
#define LL    4096
#define HALFL 2048
#define CHUNK 16            // j per thread: l = 2048*half + t + 128*j
#define NPAIR 16            // packed n-pairs
#define NT    2             // j-tiles of 8 per thread

// W = dA^128.  l = 2048*half + t + 128*(8*jt + r)
// x = Re( v * E * W^{8jt} * W^r ),  v = 2*Ceff*dA^t,  E = dA^{2048*half}
//   = Vr[jt]*c_r + Vi[jt]*d_r,  c_r = Re(W^r), d_r = -Im(W^r)
// Coeffs block-uniform in SMEM: 1 broadcast LDS.128 feeds 4 independent FFMA2.

typedef unsigned long long u64;

__device__ __forceinline__ u64 pk2(float lo, float hi) {
    u64 r; asm("mov.b64 %0, {%1,%2};" : "=l"(r) : "f"(lo), "f"(hi)); return r;
}
__device__ __forceinline__ void upk2(float& lo, float& hi, u64 v) {
    asm("mov.b64 {%0,%1}, %2;" : "=f"(lo), "=f"(hi) : "l"(v));
}
__device__ __forceinline__ u64 mul2(u64 a, u64 b) {
    u64 r; asm("mul.rn.f32x2 %0, %1, %2;" : "=l"(r) : "l"(a), "l"(b)); return r;
}
__device__ __forceinline__ u64 fma2(u64 a, u64 b, u64 c) {
    u64 r; asm("fma.rn.f32x2 %0, %1, %2, %3;" : "=l"(r) : "l"(a), "l"(b), "l"(c)); return r;
}
__device__ __forceinline__ u64 add2(u64 a, u64 b) {
    u64 r; asm("add.rn.f32x2 %0, %1, %2;" : "=l"(r) : "l"(a), "l"(b)); return r;
}

__global__ void __launch_bounds__(TPB, 6)
sskernel_diag(const float* __restrict__ log_dt,
              const float* __restrict__ B_ri,
              const float* __restrict__ C_ri,
              const float* __restrict__ inv_A_real,
              const float* __restrict__ A_imag,
              float* __restrict__ out)
{
    __shared__ float s_lg[NH], s_th[NH];       // log|dA|, arg(dA)
    __shared__ float s_cr[NH], s_ci[NH];       // 2*Ceff
    __shared__ float s_er[NH], s_ei[NH];       // E = dA^{2048*half}
    // Per pair p: entry 0 = {Re(W^8), -Im(W^8)}; r=1..7 = {c_r, d_r} packed.
    __shared__ ulonglong2 s_tab[NPAIR][8];     // 2 KB
    __shared__ u64 s_w8b[NPAIR];               // +Im(W^8) packed

    const int h    = blockIdx.x >> 1;
    const int half = blockIdx.x & 1;
    const int t    = threadIdx.x;

    // ---- per-(h,n) setup in fp64 (threads 0..31, one n each) ----
    if (t < NH) {
        const int n  = t;
        const int hn = h * NH + n;
        const int p  = n >> 1, lane = n & 1;
        double dt = exp((double)log_dt[h]);
        double Ar = -exp((double)inv_A_real[hn]);
        double Ai = (double)A_imag[hn];
        double zr = Ar * dt, zi = Ai * dt;                 // dtA
        double dr = 1.0 - 0.5 * zr, di = -0.5 * zi;        // 1 - dtA/2
        double d2 = dr * dr + di * di;
        double idr =  dr / d2, idi = -di / d2;             // 1/(1-dtA/2)
        double nr = 1.0 + 0.5 * zr, ni = 0.5 * zi;         // 1 + dtA/2
        double dAr = nr * idr - ni * idi;                  // bilinear dA
        double dAi = nr * idi + ni * idr;
        double Br = (double)B_ri[2 * hn],  Bi = (double)B_ri[2 * hn + 1];
        double Cr = (double)C_ri[2 * hn],  Ci = (double)C_ri[2 * hn + 1];
        double bcr = Br * Cr - Bi * Ci,    bci = Br * Ci + Bi * Cr;
        s_cr[n] = (float)(2.0 * (bcr * idr - bci * idi) * dt);   // 2*Ceff
        s_ci[n] = (float)(2.0 * (bcr * idi + bci * idr) * dt);
        s_lg[n] = (float)(0.5 * log(dAr * dAr + dAi * dAi));
        s_th[n] = (float)atan2(dAi, dAr);
        // W = dA^128 via 7 complex squarings (fp64)
        double wr = dAr, wi = dAi;
        #pragma unroll
        for (int s = 0; s < 7; s++) {
            double tr = wr * wr - wi * wi;
            double ti = 2.0 * wr * wi;
            wr = tr; wi = ti;
        }
        // powers W^1..W^7 into table, then W^8
        float* tf = (float*)s_tab;
        double cr_ = wr, ci_ = wi;
        #pragma unroll
        for (int r = 1; r < 8; r++) {
            const int base = (p * 8 + r) * 4;
            tf[base + lane]     = (float)cr_;        // c_r = Re(W^r)
            tf[base + 2 + lane] = (float)(-ci_);     // d_r = -Im(W^r)
            double tr = cr_ * wr - ci_ * wi;
            ci_ = cr_ * wi + ci_ * wr; cr_ = tr;
        }
        // entry 0: W^8 = (a, b) stored as {a, -b}; +b in side table
        tf[(p * 8) * 4 + lane]     = (float)cr_;
        tf[(p * 8) * 4 + 2 + lane] = (float)(-ci_);
        ((float*)s_w8b)[p * 2 + lane] = (float)ci_;
        // (W^8) = dA^1024 -> E = dA^2048 = (W^8)^2 when half==1
        if (half) {
            double er = cr_ * cr_ - ci_ * ci_;       // dA^2048
            double ei = 2.0 * cr_ * ci_;
            s_er[n] = (float)er; s_ei[n] = (float)ei;
        } else {
            s_er[n] = 1.0f; s_ei[n] = 0.0f;
        }
    }
    __syncthreads();

    // ---- main ----
    u64 acc[CHUNK];
    #pragma unroll
    for (int j = 0; j < CHUNK; j++) acc[j] = 0ull;

    const float l0 = (float)t;

    for (int p = 0; p < NPAIR; p++) {
        // v_n = 2*Ceff_n * dA_n^t * E_n  (t < 128 keeps MUFU args accurate)
        float vr[2], vi[2];
        #pragma unroll
        for (int k = 0; k < 2; k++) {
            const int n = 2 * p + k;
            const float cr = s_cr[n], ci = s_ci[n];
            float e = __expf(l0 * s_lg[n]);
            float sn, cs;
            __sincosf(l0 * s_th[n], &sn, &cs);
            float ur = e * (cr * cs - ci * sn);
            float ui = e * (ci * cs + cr * sn);
            const float er = s_er[n], ei = s_ei[n];
            vr[k] = ur * er - ui * ei;
            vi[k] = ur * ei + ui * er;
        }

        const ulonglong2* tp = &s_tab[p][0];
        const ulonglong2 e0 = tp[0];
        const u64 A  = e0.x;           // Re(W^8)
        const u64 NB = e0.y;           // -Im(W^8)
        const u64 Bq = s_w8b[p];       // +Im(W^8)

        // Tile states V[jt] = v * W^{8jt}, jt = 0..1
        u64 Vr[NT], Vi[NT];
        Vr[0] = pk2(vr[0], vr[1]);
        Vi[0] = pk2(vi[0], vi[1]);
        Vr[1] = fma2(Vi[0], NB, mul2(Vr[0], A));
        Vi[1] = fma2(Vi[0], A,  mul2(Vr[0], Bq));

        // r = 0
        acc[0] = add2(acc[0], Vr[0]);
        acc[8] = add2(acc[8], Vr[1]);

        // r = 1..7: one broadcast LDS.128 -> 4 independent FFMA2
        #pragma unroll
        for (int r = 1; r < 8; r++) {
            const ulonglong2 q = tp[r];      // (c_r, d_r)
            acc[r]     = fma2(Vr[0], q.x, fma2(Vi[0], q.y, acc[r]));
            acc[8 + r] = fma2(Vr[1], q.x, fma2(Vi[1], q.y, acc[8 + r]));
        }
    }

    // ---- coalesced stores (2x folded into Ceff) ----
    float* o = out + (size_t)h * LL + half * HALFL + t;
    #pragma unroll
    for (int j = 0; j < CHUNK; j++) {
        float lo, hi;
        upk2(lo, hi, acc[j]);
        o[j * TPB] = lo + hi;
    }
}

extern "C" void kernel_launch(void* const* d_in, const int* in_sizes, int n_in,
                              void* d_out, int out_size)
{
    const float* log_dt     = (const float*)d_in[0];   // (H,)
    const float* B_ri       = (const float*)d_in[1];   // (H, N, 2)
    const float* C_ri       = (const float*)d_in[2];   // (1, H, N, 2)
    const float* inv_A_real = (const float*)d_in[3];   // (H, N)
    const float* A_imag     = (const float*)d_in[4];   // (H, N)
    float* out = (float*)d_out;                        // (1, H, L)

    sskernel_diag<<<2 * HH, TPB>>>(log_dt, B_ri, C_ri, inv_A_real, A_imag, out);
}

// round 13
// speedup vs baseline: 2.0703x; 2.0703x over previous
#include <cuda_runtime.h>
#include <math.h>

// Shape-specialized: H=1024, N_HALF=32, L=4096, CHANNELS=1
// Grid = 1024 (one block per h), TPB=128, 7 blocks/SM -> FULL grid residency.
#define HH    1024
#define NH    32
#define TPB   128
#define LL    4096

// l = t + 128*(jt*8 + r), jt in 0..3, r in 0..7.  W = dA^128.
// x = Re( v * W^{8jt} * W^r ) = Vr[jt]*c_r + Vi[jt]*d_r,
//   c_r = Re(W^r), d_r = -Im(W^r).
// j-tile pairs packed per f32x2 reg with DUPLICATED coefficients:
//   acc(jt0,jt1)[r] = fma2({Vr0,Vr1}, {c,c}, fma2({Vi0,Vi1}, {d,d}, acc))
// -> 1 broadcast LDS.128 feeds 4 independent FFMA2; acc = 16 u64 = 32 regs.

typedef unsigned long long u64;

__device__ __forceinline__ u64 pk2(float lo, float hi) {
    u64 r; asm("mov.b64 %0, {%1,%2};" : "=l"(r) : "f"(lo), "f"(hi)); return r;
}
__device__ __forceinline__ void upk2(float& lo, float& hi, u64 v) {
    asm("mov.b64 {%0,%1}, %2;" : "=f"(lo), "=f"(hi) : "l"(v));
}
__device__ __forceinline__ u64 mul2(u64 a, u64 b) {
    u64 r; asm("mul.rn.f32x2 %0, %1, %2;" : "=l"(r) : "l"(a), "l"(b)); return r;
}
__device__ __forceinline__ u64 fma2(u64 a, u64 b, u64 c) {
    u64 r; asm("fma.rn.f32x2 %0, %1, %2, %3;" : "=l"(r) : "l"(a), "l"(b), "l"(c)); return r;
}
__device__ __forceinline__ u64 add2(u64 a, u64 b) {
    u64 r; asm("add.rn.f32x2 %0, %1, %2;" : "=l"(r) : "l"(a), "l"(b)); return r;
}

__global__ void __launch_bounds__(TPB, 7)
sskernel_diag(const float* __restrict__ log_dt,
              const float* __restrict__ B_ri,
              const float* __restrict__ C_ri,
              const float* __restrict__ inv_A_real,
              const float* __restrict__ A_imag,
              float* __restrict__ out)
{
    __shared__ float s_lg[NH], s_th[NH];       // log|dA|, arg(dA)
    __shared__ float s_cr[NH], s_ci[NH];       // 2*Ceff
    __shared__ float s_w8r[NH], s_w8i[NH];     // W^8 scalar
    // s_tab[n][0]   = {a16, a16, -b16, -b16}   (W^16 duplicated)
    // s_tab[n][1..7]= {c_r, c_r,  d_r,  d_r}   (c=Re W^r, d=-Im W^r)
    __shared__ ulonglong2 s_tab[NH][8];        // 4 KB
    __shared__ u64 s_w16pb[NH];                // {+b16, +b16}

    const int h = blockIdx.x;
    const int t = threadIdx.x;

    // ---- per-(h,n) setup in fp64 (threads 0..31, one n each) ----
    if (t < NH) {
        const int n  = t;
        const int hn = h * NH + n;
        double dt = exp((double)log_dt[h]);
        double Ar = -exp((double)inv_A_real[hn]);
        double Ai = (double)A_imag[hn];
        double zr = Ar * dt, zi = Ai * dt;                 // dtA
        double dr = 1.0 - 0.5 * zr, di = -0.5 * zi;        // 1 - dtA/2
        double d2 = dr * dr + di * di;
        double idr =  dr / d2, idi = -di / d2;             // 1/(1-dtA/2)
        double nr = 1.0 + 0.5 * zr, ni = 0.5 * zi;         // 1 + dtA/2
        double dAr = nr * idr - ni * idi;                  // bilinear dA
        double dAi = nr * idi + ni * idr;
        double Br = (double)B_ri[2 * hn],  Bi = (double)B_ri[2 * hn + 1];
        double Cr = (double)C_ri[2 * hn],  Ci = (double)C_ri[2 * hn + 1];
        double bcr = Br * Cr - Bi * Ci,    bci = Br * Ci + Bi * Cr;
        s_cr[n] = (float)(2.0 * (bcr * idr - bci * idi) * dt);   // 2*Ceff
        s_ci[n] = (float)(2.0 * (bcr * idi + bci * idr) * dt);
        s_lg[n] = (float)(0.5 * log(dAr * dAr + dAi * dAi));
        s_th[n] = (float)atan2(dAi, dAr);
        // W = dA^128 via 7 complex squarings (fp64)
        double wr = dAr, wi = dAi;
        #pragma unroll
        for (int s = 0; s < 7; s++) {
            double tr = wr * wr - wi * wi;
            double ti = 2.0 * wr * wi;
            wr = tr; wi = ti;
        }
        // W^1..W^7 duplicated into table; then W^8, W^16
        double pr = wr, pi = wi;
        #pragma unroll
        for (int r = 1; r < 8; r++) {
            float* tf = (float*)&s_tab[n][r];
            tf[0] = (float)pr;  tf[1] = (float)pr;     // c_r
            tf[2] = (float)(-pi); tf[3] = (float)(-pi); // d_r
            double tr = pr * wr - pi * wi;
            pi = pr * wi + pi * wr; pr = tr;
        }
        s_w8r[n] = (float)pr;                           // W^8
        s_w8i[n] = (float)pi;
        double a16 = pr * pr - pi * pi;                 // W^16
        double b16 = 2.0 * pr * pi;
        {
            float* tf = (float*)&s_tab[n][0];
            tf[0] = (float)a16;   tf[1] = (float)a16;
            tf[2] = (float)(-b16); tf[3] = (float)(-b16);
            float* pb = (float*)&s_w16pb[n];
            pb[0] = (float)b16;   pb[1] = (float)b16;
        }
    }
    __syncthreads();

    // ---- main ----
    u64 acc[16];                 // acc[r] = (jt0,jt1); acc[8+r] = (jt2,jt3)
    #pragma unroll
    for (int j = 0; j < 16; j++) acc[j] = 0ull;

    const float l0 = (float)t;

    for (int n = 0; n < NH; n++) {
        // v = 2*Ceff * dA^t   (t < 128: MUFU args stay accurate)
        const float cr = s_cr[n], ci = s_ci[n];
        float e = __expf(l0 * s_lg[n]);
        float sn, cs;
        __sincosf(l0 * s_th[n], &sn, &cs);
        const float vr = e * (cr * cs - ci * sn);
        const float vi = e * (ci * cs + cr * sn);
        // V pair (jt0, jt1) = (v, v*W^8)
        const float a8 = s_w8r[n], b8 = s_w8i[n];
        const float vr1 = vr * a8 - vi * b8;
        const float vi1 = vr * b8 + vi * a8;
        const u64 Vr01 = pk2(vr, vr1);
        const u64 Vi01 = pk2(vi, vi1);
        // V pair (jt2, jt3) = V01 * W^16 (duplicated coeff)
        const ulonglong2 w16 = s_tab[n][0];   // {A16dup, -B16dup}
        const u64 Bp = s_w16pb[n];            // {+B16dup}
        const u64 Vr23 = fma2(Vi01, w16.y, mul2(Vr01, w16.x));
        const u64 Vi23 = fma2(Vi01, w16.x, mul2(Vr01, Bp));

        // r = 0
        acc[0] = add2(acc[0], Vr01);
        acc[8] = add2(acc[8], Vr23);

        // r = 1..7: one broadcast LDS.128 -> 4 independent FFMA2
        #pragma unroll
        for (int r = 1; r < 8; r++) {
            const ulonglong2 q = s_tab[n][r];   // {c_dup, d_dup}
            acc[r]     = fma2(Vr01, q.x, fma2(Vi01, q.y, acc[r]));
            acc[8 + r] = fma2(Vr23, q.x, fma2(Vi23, q.y, acc[8 + r]));
        }
    }

    // ---- coalesced stores (2x folded into Ceff) ----
    // acc[r]: lo -> j=r, hi -> j=8+r ; acc[8+r]: lo -> j=16+r, hi -> j=24+r
    float* o = out + (size_t)h * LL + t;
    #pragma unroll
    for (int r = 0; r < 8; r++) {
        float lo, hi;
        upk2(lo, hi, acc[r]);
        o[r * TPB]        = lo;
        o[(8 + r) * TPB]  = hi;
        upk2(lo, hi, acc[8 + r]);
        o[(16 + r) * TPB] = lo;
        o[(24 + r) * TPB] = hi;
    }
}

extern "C" void kernel_launch(void* const* d_in, const int* in_sizes, int n_in,
                              void* d_out, int out_size)
{
    const float* log_dt     = (const float*)d_in[0];   // (H,)
    const float* B_ri       = (const float*)d_in[1];   // (H, N, 2)
    const float* C_ri       = (const float*)d_in[2];   // (1, H, N, 2)
    const float* inv_A_real = (const float*)d_in[3];   // (H, N)
    const float* A_imag     = (const float*)d_in[4];   // (H, N)
    float* out = (float*)d_out;                        // (1, H, L)

    sskernel_diag<<<HH, TPB>>>(log_dt, B_ri, C_ri, inv_A_real, A_imag, out);
}

// round 14
// speedup vs baseline: 3.4628x; 1.6726x over previous
#include <cuda_runtime.h>
#include <math.h>

// Shape-specialized: H=1024, N_HALF=32, L=4096, CHANNELS=1
// Grid = 1024 (one block per h), TPB=128, 7 blocks/SM -> FULL grid residency.
// ALL setup in fp32 (reference is fp32/complex64 itself; fp64 exp/log/atan2
// software sequences were ~25us of hidden FP64-pipe background per round).
#define HH    1024
#define NH    32
#define TPB   128
#define LL    4096

// l = t + 128*(jt*8 + r), jt in 0..3, r in 0..7.  W = dA^128.
// x = Re( v * W^{8jt} * W^r ) = Vr[jt]*c_r + Vi[jt]*d_r,
//   c_r = Re(W^r), d_r = -Im(W^r).
// j-tile pairs packed per f32x2 reg with DUPLICATED coefficients:
//   acc(jt0,jt1)[r] = fma2({Vr0,Vr1}, {c,c}, fma2({Vi0,Vi1}, {d,d}, acc))
// 1 broadcast LDS.128 feeds 4 independent FFMA2; acc = 16 u64 = 32 regs.

typedef unsigned long long u64;

__device__ __forceinline__ u64 pk2(float lo, float hi) {
    u64 r; asm("mov.b64 %0, {%1,%2};" : "=l"(r) : "f"(lo), "f"(hi)); return r;
}
__device__ __forceinline__ void upk2(float& lo, float& hi, u64 v) {
    asm("mov.b64 {%0,%1}, %2;" : "=f"(lo), "=f"(hi) : "l"(v));
}
__device__ __forceinline__ u64 mul2(u64 a, u64 b) {
    u64 r; asm("mul.rn.f32x2 %0, %1, %2;" : "=l"(r) : "l"(a), "l"(b)); return r;
}
__device__ __forceinline__ u64 fma2(u64 a, u64 b, u64 c) {
    u64 r; asm("fma.rn.f32x2 %0, %1, %2, %3;" : "=l"(r) : "l"(a), "l"(b), "l"(c)); return r;
}
__device__ __forceinline__ u64 add2(u64 a, u64 b) {
    u64 r; asm("add.rn.f32x2 %0, %1, %2;" : "=l"(r) : "l"(a), "l"(b)); return r;
}

__global__ void __launch_bounds__(TPB, 7)
sskernel_diag(const float* __restrict__ log_dt,
              const float* __restrict__ B_ri,
              const float* __restrict__ C_ri,
              const float* __restrict__ inv_A_real,
              const float* __restrict__ A_imag,
              float* __restrict__ out)
{
    __shared__ float s_lg[NH], s_th[NH];       // log|dA|, arg(dA)
    __shared__ float s_cr[NH], s_ci[NH];       // 2*Ceff
    __shared__ float s_w8r[NH], s_w8i[NH];     // W^8
    // s_tab[n][0]   = {a16, a16, -b16, -b16}   (W^16 duplicated)
    // s_tab[n][1..7]= {c_r, c_r,  d_r,  d_r}   (c=Re W^r, d=-Im W^r)
    __shared__ ulonglong2 s_tab[NH][8];        // 4 KB
    __shared__ u64 s_w16pb[NH];                // {+b16, +b16}

    const int h = blockIdx.x;
    const int t = threadIdx.x;

    // ---- phase 1: per-(h,n) base params, ALL fp32 (threads 0..31) ----
    if (t < NH) {
        const int n  = t;
        const int hn = h * NH + n;
        float dt = expf(log_dt[h]);
        float Ar = -expf(inv_A_real[hn]);
        float Ai = A_imag[hn];
        float zr = Ar * dt, zi = Ai * dt;                  // dtA
        float dr = 1.0f - 0.5f * zr, di = -0.5f * zi;      // 1 - dtA/2
        float inv = 1.0f / (dr * dr + di * di);
        float idr =  dr * inv, idi = -di * inv;            // 1/(1-dtA/2)
        float nr = 1.0f + 0.5f * zr, ni = 0.5f * zi;       // 1 + dtA/2
        float dAr = nr * idr - ni * idi;                   // bilinear dA
        float dAi = nr * idi + ni * idr;
        float Br = B_ri[2 * hn],  Bi = B_ri[2 * hn + 1];
        float Cr = C_ri[2 * hn],  Ci = C_ri[2 * hn + 1];
        float bcr = Br * Cr - Bi * Ci, bci = Br * Ci + Bi * Cr;
        s_cr[n] = 2.0f * (bcr * idr - bci * idi) * dt;     // 2*Ceff
        s_ci[n] = 2.0f * (bcr * idi + bci * idr) * dt;
        s_lg[n] = 0.5f * logf(dAr * dAr + dAi * dAi);
        s_th[n] = atan2f(dAi, dAr);
    }
    __syncthreads();

    // ---- phase 2: coefficient table, all 128 threads (n = t&31, g = t>>5) ----
    // Powers needed per n: W^{128*pw}, pw in {1..8, 16}. Each entry from
    // exp(128*pw*lg) * cis(128*pw*th) — absolute accuracy only.
    {
        const int n = t & 31, g = t >> 5;
        const float lg = s_lg[n], th = s_th[n];
        #pragma unroll
        for (int k = g; k < 9; k += 4) {
            const int pw = (k < 8) ? (k + 1) : 16;
            const float fp = 128.0f * (float)pw;
            float m = __expf(fp * lg);
            float sn, cs;
            __sincosf(fp * th, &sn, &cs);
            const float a = m * cs, b = m * sn;
            if (pw < 8) {
                float* tf = (float*)&s_tab[n][pw];
                tf[0] = a;  tf[1] = a;
                tf[2] = -b; tf[3] = -b;
            } else if (pw == 8) {
                s_w8r[n] = a; s_w8i[n] = b;
            } else {                         // pw == 16
                float* tf = (float*)&s_tab[n][0];
                tf[0] = a;  tf[1] = a;
                tf[2] = -b; tf[3] = -b;
                float* pb = (float*)&s_w16pb[n];
                pb[0] = b;  pb[1] = b;
            }
        }
    }
    __syncthreads();

    // ---- main ----
    u64 acc[16];                 // acc[r] = (jt0,jt1); acc[8+r] = (jt2,jt3)
    #pragma unroll
    for (int j = 0; j < 16; j++) acc[j] = 0ull;

    const float l0 = (float)t;

    for (int n = 0; n < NH; n++) {
        // v = 2*Ceff * dA^t   (t < 128: MUFU args stay accurate)
        const float cr = s_cr[n], ci = s_ci[n];
        float e = __expf(l0 * s_lg[n]);
        float sn, cs;
        __sincosf(l0 * s_th[n], &sn, &cs);
        const float vr = e * (cr * cs - ci * sn);
        const float vi = e * (ci * cs + cr * sn);
        // V pair (jt0, jt1) = (v, v*W^8)
        const float a8 = s_w8r[n], b8 = s_w8i[n];
        const float vr1 = vr * a8 - vi * b8;
        const float vi1 = vr * b8 + vi * a8;
        const u64 Vr01 = pk2(vr, vr1);
        const u64 Vi01 = pk2(vi, vi1);
        // V pair (jt2, jt3) = V01 * W^16 (duplicated coeff)
        const ulonglong2 w16 = s_tab[n][0];   // {A16dup, -B16dup}
        const u64 Bp = s_w16pb[n];            // {+B16dup}
        const u64 Vr23 = fma2(Vi01, w16.y, mul2(Vr01, w16.x));
        const u64 Vi23 = fma2(Vi01, w16.x, mul2(Vr01, Bp));

        // r = 0
        acc[0] = add2(acc[0], Vr01);
        acc[8] = add2(acc[8], Vr23);

        // r = 1..7: one broadcast LDS.128 -> 4 independent FFMA2
        #pragma unroll
        for (int r = 1; r < 8; r++) {
            const ulonglong2 q = s_tab[n][r];   // {c_dup, d_dup}
            acc[r]     = fma2(Vr01, q.x, fma2(Vi01, q.y, acc[r]));
            acc[8 + r] = fma2(Vr23, q.x, fma2(Vi23, q.y, acc[8 + r]));
        }
    }

    // ---- coalesced stores (2x folded into Ceff) ----
    // acc[r]: lo -> j=r, hi -> j=8+r ; acc[8+r]: lo -> j=16+r, hi -> j=24+r
    float* o = out + (size_t)h * LL + t;
    #pragma unroll
    for (int r = 0; r < 8; r++) {
        float lo, hi;
        upk2(lo, hi, acc[r]);
        o[r * TPB]        = lo;
        o[(8 + r) * TPB]  = hi;
        upk2(lo, hi, acc[8 + r]);
        o[(16 + r) * TPB] = lo;
        o[(24 + r) * TPB] = hi;
    }
}

extern "C" void kernel_launch(void* const* d_in, const int* in_sizes, int n_in,
                              void* d_out, int out_size)
{
    const float* log_dt     = (const float*)d_in[0];   // (H,)
    const float* B_ri       = (const float*)d_in[1];   // (H, N, 2)
    const float* C_ri       = (const float*)d_in[2];   // (1, H, N, 2)
    const float* inv_A_real = (const float*)d_in[3];   // (H, N)
    const float* A_imag     = (const float*)d_in[4];   // (H, N)
    float* out = (float*)d_out;                        // (1, H, L)

    sskernel_diag<<<HH, TPB>>>(log_dt, B_ri, C_ri, inv_A_real, A_imag, out);
}

// round 15
// speedup vs baseline: 3.5527x; 1.0260x over previous
#include <cuda_runtime.h>
#include <math.h>

// Shape-specialized: H=1024, N_HALF=32, L=4096, CHANNELS=1
// Grid = 1024 (one block per h), TPB=128, 7 blocks/SM -> FULL grid residency.
// All setup fp32 (fp64 software sequences cost ~25us background - R14 finding).
#define HH    1024
#define NH    32
#define TPB   128
#define LL    4096

// l = t + 128*(jt*8 + r), jt in 0..3, r in 0..7.  W = dA^128.
// x = Re( v * W^{8jt} * W^r ) = Vr[jt]*c_r + Vi[jt]*d_r,
//   c_r = Re(W^r), d_r = -Im(W^r).
// j-tile pairs packed per f32x2 reg with DUPLICATED coefficients:
// 1 broadcast LDS.128 feeds 4 independent FFMA2; acc = 16 u64 = 32 regs.
// Per-n scalars packed: float4 {2Cr,2Ci,lg,th} + float2 {W8r,W8i}.

typedef unsigned long long u64;

__device__ __forceinline__ u64 pk2(float lo, float hi) {
    u64 r; asm("mov.b64 %0, {%1,%2};" : "=l"(r) : "f"(lo), "f"(hi)); return r;
}
__device__ __forceinline__ void upk2(float& lo, float& hi, u64 v) {
    asm("mov.b64 {%0,%1}, %2;" : "=f"(lo), "=f"(hi) : "l"(v));
}
__device__ __forceinline__ u64 mul2(u64 a, u64 b) {
    u64 r; asm("mul.rn.f32x2 %0, %1, %2;" : "=l"(r) : "l"(a), "l"(b)); return r;
}
__device__ __forceinline__ u64 fma2(u64 a, u64 b, u64 c) {
    u64 r; asm("fma.rn.f32x2 %0, %1, %2, %3;" : "=l"(r) : "l"(a), "l"(b), "l"(c)); return r;
}
__device__ __forceinline__ u64 add2(u64 a, u64 b) {
    u64 r; asm("add.rn.f32x2 %0, %1, %2;" : "=l"(r) : "l"(a), "l"(b)); return r;
}

__global__ void __launch_bounds__(TPB, 7)
sskernel_diag(const float* __restrict__ log_dt,
              const float* __restrict__ B_ri,
              const float* __restrict__ C_ri,
              const float* __restrict__ inv_A_real,
              const float* __restrict__ A_imag,
              float* __restrict__ out)
{
    __shared__ float4 s_par[NH];               // {2Ceff_r, 2Ceff_i, lg, th}
    __shared__ float2 s_w8[NH];                // {Re W^8, Im W^8}
    // s_tab[n][0]   = {a16, a16, -b16, -b16}   (W^16 duplicated)
    // s_tab[n][1..7]= {c_r, c_r,  d_r,  d_r}   (c=Re W^r, d=-Im W^r)
    __shared__ ulonglong2 s_tab[NH][8];        // 4 KB
    __shared__ u64 s_w16pb[NH];                // {+b16, +b16}

    const int h = blockIdx.x;
    const int t = threadIdx.x;

    // ---- phase 1: per-(h,n) base params, fp32 (threads 0..31) ----
    if (t < NH) {
        const int n  = t;
        const int hn = h * NH + n;
        float dt = expf(log_dt[h]);
        float Ar = -expf(inv_A_real[hn]);
        float Ai = A_imag[hn];
        float zr = Ar * dt, zi = Ai * dt;                  // dtA
        float dr = 1.0f - 0.5f * zr, di = -0.5f * zi;      // 1 - dtA/2
        float inv = 1.0f / (dr * dr + di * di);
        float idr =  dr * inv, idi = -di * inv;            // 1/(1-dtA/2)
        float nr = 1.0f + 0.5f * zr, ni = 0.5f * zi;       // 1 + dtA/2
        float dAr = nr * idr - ni * idi;                   // bilinear dA
        float dAi = nr * idi + ni * idr;
        float Br = B_ri[2 * hn],  Bi = B_ri[2 * hn + 1];
        float Cr = C_ri[2 * hn],  Ci = C_ri[2 * hn + 1];
        float bcr = Br * Cr - Bi * Ci, bci = Br * Ci + Bi * Cr;
        float4 par;
        par.x = 2.0f * (bcr * idr - bci * idi) * dt;       // 2*Ceff_r
        par.y = 2.0f * (bcr * idi + bci * idr) * dt;       // 2*Ceff_i
        par.z = 0.5f * logf(dAr * dAr + dAi * dAi);        // lg
        par.w = atan2f(dAi, dAr);                          // th
        s_par[n] = par;
    }
    __syncthreads();

    // ---- phase 2: coefficient table, all 128 threads (n = t&31, g = t>>5) ----
    // Powers W^{pw} = dA^{128*pw}, pw in {1..8, 16}, from exp/cis directly.
    {
        const int n = t & 31, g = t >> 5;
        const float lg = s_par[n].z, th = s_par[n].w;
        #pragma unroll
        for (int k = g; k < 9; k += 4) {
            const int pw = (k < 8) ? (k + 1) : 16;
            const float fp = 128.0f * (float)pw;
            float m = __expf(fp * lg);
            float sn, cs;
            __sincosf(fp * th, &sn, &cs);
            const float a = m * cs, b = m * sn;
            if (pw < 8) {
                float* tf = (float*)&s_tab[n][pw];
                tf[0] = a;  tf[1] = a;
                tf[2] = -b; tf[3] = -b;
            } else if (pw == 8) {
                s_w8[n] = make_float2(a, b);
            } else {                         // pw == 16
                float* tf = (float*)&s_tab[n][0];
                tf[0] = a;  tf[1] = a;
                tf[2] = -b; tf[3] = -b;
                float* pb = (float*)&s_w16pb[n];
                pb[0] = b;  pb[1] = b;
            }
        }
    }
    __syncthreads();

    // ---- main ----
    u64 acc[16];                 // acc[r] = (jt0,jt1); acc[8+r] = (jt2,jt3)
    #pragma unroll
    for (int j = 0; j < 16; j++) acc[j] = 0ull;

    const float l0 = (float)t;

    for (int n = 0; n < NH; n++) {
        // v = 2*Ceff * dA^t   (t < 128: MUFU args stay accurate)
        const float4 P = s_par[n];               // one LDS.128
        float e = __expf(l0 * P.z);
        float sn, cs;
        __sincosf(l0 * P.w, &sn, &cs);
        const float vr = e * (P.x * cs - P.y * sn);
        const float vi = e * (P.y * cs + P.x * sn);
        // V pair (jt0, jt1) = (v, v*W^8)
        const float2 w8 = s_w8[n];               // one LDS.64
        const float vr1 = vr * w8.x - vi * w8.y;
        const float vi1 = vr * w8.y + vi * w8.x;
        const u64 Vr01 = pk2(vr, vr1);
        const u64 Vi01 = pk2(vi, vi1);
        // V pair (jt2, jt3) = V01 * W^16 (duplicated coeff)
        const ulonglong2 w16 = s_tab[n][0];      // {A16dup, -B16dup}
        const u64 Bp = s_w16pb[n];               // {+B16dup}
        const u64 Vr23 = fma2(Vi01, w16.y, mul2(Vr01, w16.x));
        const u64 Vi23 = fma2(Vi01, w16.x, mul2(Vr01, Bp));

        // r = 0
        acc[0] = add2(acc[0], Vr01);
        acc[8] = add2(acc[8], Vr23);

        // r = 1..7: one broadcast LDS.128 -> 4 independent FFMA2
        #pragma unroll
        for (int r = 1; r < 8; r++) {
            const ulonglong2 q = s_tab[n][r];    // {c_dup, d_dup}
            acc[r]     = fma2(Vr01, q.x, fma2(Vi01, q.y, acc[r]));
            acc[8 + r] = fma2(Vr23, q.x, fma2(Vi23, q.y, acc[8 + r]));
        }
    }

    // ---- coalesced stores (2x folded into Ceff) ----
    // acc[r]: lo -> j=r, hi -> j=8+r ; acc[8+r]: lo -> j=16+r, hi -> j=24+r
    float* o = out + (size_t)h * LL + t;
    #pragma unroll
    for (int r = 0; r < 8; r++) {
        float lo, hi;
        upk2(lo, hi, acc[r]);
        o[r * TPB]        = lo;
        o[(8 + r) * TPB]  = hi;
        upk2(lo, hi, acc[8 + r]);
        o[(16 + r) * TPB] = lo;
        o[(24 + r) * TPB] = hi;
    }
}

extern "C" void kernel_launch(void* const* d_in, const int* in_sizes, int n_in,
                              void* d_out, int out_size)
{
    const float* log_dt     = (const float*)d_in[0];   // (H,)
    const float* B_ri       = (const float*)d_in[1];   // (H, N, 2)
    const float* C_ri       = (const float*)d_in[2];   // (1, H, N, 2)
    const float* inv_A_real = (const float*)d_in[3];   // (H, N)
    const float* A_imag     = (const float*)d_in[4];   // (H, N)
    float* out = (float*)d_out;                        // (1, H, L)

    sskernel_diag<<<HH, TPB>>>(log_dt, B_ri, C_ri, inv_A_real, A_imag, out);
}